// round 13
// baseline (speedup 1.0000x reference)
#include <cuda_runtime.h>
#include <cuda_fp16.h>
#include <stdint.h>

#define CH 64
#define HH 224
#define WW 224
#define HW (HH*WW)

#define TPX 32          // output tile width
#define TRY 8           // output tile rows
#define IW  34          // staged input width  (x0-1 .. x0+32)
#define IR  10          // staged input rows   (y0-1 .. y0+8)

#define P_BYTES (IR*IW*128)                 // 43520: fp16 plane [(r,q)][ci 0..63]
#define OFF_WB  ((uint32_t)P_BYTES)         // weight tap ring: 2 x 8192 B
#define SMEM_DYN (P_BYTES + 2*8192)         // 59904 B -> 2 CTAs/SM

// B fragments pre-packed in mma.m16n8k16.f16 fragment order:
// [t][c][wn][half][lane] ; half0 = {g0,g1}, half1 = {g2,g3}  (g relative to wn*32)
// lane holds {B[k][n], B[k+1][n]} with n = wn*32+g*8+lane/4, k = 16c+(lane%4)*2+r2*8
__device__ uint4 g_wf[9 * 4 * 2 * 2 * 32];   // 73728 B (L2-resident)

__global__ void prep_wfrag(const float* __restrict__ w) {
    int idx = blockIdx.x * blockDim.x + threadIdx.x;
    if (idx >= 9 * 4 * 2 * 2 * 32) return;
    int lane = idx & 31;
    int half = (idx >> 5) & 1;
    int wn   = (idx >> 6) & 1;
    int c    = (idx >> 7) & 3;
    int t    = idx >> 9;
    uint32_t r[4];
#pragma unroll
    for (int j = 0; j < 4; j++) {
        int g  = half * 2 + (j >> 1);
        int r2 = j & 1;
        int n  = wn * 32 + g * 8 + (lane >> 2);
        int k  = c * 16 + (lane & 3) * 2 + r2 * 8;
        float v0 = w[(n * 64 + k)     * 9 + t];
        float v1 = w[(n * 64 + k + 1) * 9 + t];
        float s0 = (v0 > 0.f) ? 1.f : ((v0 < 0.f) ? -1.f : 0.f);
        float s1 = (v1 > 0.f) ? 1.f : ((v1 < 0.f) ? -1.f : 0.f);
        __half h0 = __float2half(s0), h1 = __float2half(s1);
        r[j] = (uint32_t)__half_as_ushort(h0) | ((uint32_t)__half_as_ushort(h1) << 16);
    }
    g_wf[idx] = make_uint4(r[0], r[1], r[2], r[3]);
}

__device__ __forceinline__ uint32_t smem_u32(const void* p) {
    uint32_t a;
    asm("{ .reg .u64 t; cvta.to.shared.u64 t, %1; cvt.u32.u64 %0, t; }" : "=r"(a) : "l"(p));
    return a;
}
__device__ __forceinline__ uint32_t swz(uint32_t off) {   // SW128-atom XOR swizzle
    return off ^ ((off >> 3) & 0x70);
}
__device__ __forceinline__ void sts32(uint32_t a, uint32_t v) {
    asm volatile("st.shared.b32 [%0], %1;" :: "r"(a), "r"(v));
}
__device__ __forceinline__ void sts128(uint32_t a, uint4 v) {
    asm volatile("st.shared.v4.b32 [%0], {%1,%2,%3,%4};"
                 :: "r"(a), "r"(v.x), "r"(v.y), "r"(v.z), "r"(v.w));
}
__device__ __forceinline__ uint4 lds128(uint32_t a) {
    uint4 v;
    asm volatile("ld.shared.v4.b32 {%0,%1,%2,%3}, [%4];"
                 : "=r"(v.x), "=r"(v.y), "=r"(v.z), "=r"(v.w) : "r"(a));
    return v;
}
__device__ __forceinline__ void ldm_x4(uint32_t& r0, uint32_t& r1, uint32_t& r2, uint32_t& r3,
                                       uint32_t addr) {
    asm volatile("ldmatrix.sync.aligned.m8n8.x4.shared.b16 {%0,%1,%2,%3}, [%4];"
                 : "=r"(r0), "=r"(r1), "=r"(r2), "=r"(r3) : "r"(addr));
}
__device__ __forceinline__ void mma16816(float* d, uint32_t a0, uint32_t a1, uint32_t a2,
                                         uint32_t a3, uint32_t b0, uint32_t b1) {
    asm volatile("mma.sync.aligned.m16n8k16.row.col.f32.f16.f16.f32 "
                 "{%0,%1,%2,%3},{%4,%5,%6,%7},{%8,%9},{%0,%1,%2,%3};"
                 : "+f"(d[0]), "+f"(d[1]), "+f"(d[2]), "+f"(d[3])
                 : "r"(a0), "r"(a1), "r"(a2), "r"(a3), "r"(b0), "r"(b1));
}

__global__ void __launch_bounds__(256, 2)
bconv_mma(const float* __restrict__ x, const float* __restrict__ bias,
          float* __restrict__ out)
{
    extern __shared__ char smraw[];
    const uint32_t smb = smem_u32(smraw);
    const int tid = threadIdx.x, lane = tid & 31, wid = tid >> 5;
    const int n = blockIdx.z, x0 = blockIdx.x * TPX, y0 = blockIdx.y * TRY;

    // ---- stage fp16 input plane: (10 rows x 34 px) x 32 ci-pairs, one sts32 each ----
    const float* xn = x + (size_t)n * CH * HW;
    for (int idx = tid; idx < IR * IW * 32; idx += 256) {
        int q  = idx % IW;
        int rc = idx / IW;
        int r  = rc % IR;
        int cp = rc / IR;                 // ci pair 0..31
        int gx = x0 - 1 + q, ry = y0 - 1 + r;
        float v0 = 0.f, v1 = 0.f;
        if (gx >= 0 && gx < WW && ry >= 0 && ry < HH) {
            const float* p = xn + (size_t)(cp * 2) * HW + (size_t)ry * WW + gx;
            v0 = __ldg(p);
            v1 = __ldg(p + HW);
        }
        __half h0 = __float2half(v0), h1 = __float2half(v1);
        uint32_t hp = (uint32_t)__half_as_ushort(h0) | ((uint32_t)__half_as_ushort(h1) << 16);
        sts32(smb + swz((uint32_t)(r * IW + q) * 128u + (uint32_t)cp * 4u), hp);
    }

    // ---- prime weight tap ring: tap 0 -> buf 0 (512 uint4, coalesced) ----
    {
        const uint4* wp = g_wf;
#pragma unroll
        for (int i = tid; i < 512; i += 256)
            sts128(smb + OFF_WB + (uint32_t)i * 16u, __ldg(wp + i));
    }
    __syncthreads();

    // ---- warp tiling: M32 x N64 — warp wid owns output row y0+wid, all 64 co ----
    // A fragment chunks: xh in {0,1} -> px [xh*16, xh*16+16)
    const uint32_t acol = ((uint32_t)lane >> 4) * 16u;    // k-halves for A
    const uint32_t alx  = (uint32_t)(lane & 15);
    const uint32_t bln  = (uint32_t)lane * 16u;

    float acc[2][8][4];
#pragma unroll
    for (int xh = 0; xh < 2; xh++)
#pragma unroll
        for (int g = 0; g < 8; g++)
#pragma unroll
            for (int r = 0; r < 4; r++) acc[xh][g][r] = 0.f;

#pragma unroll
    for (int t = 0; t < 9; t++) {
        // prefetch next tap's fragments into the other ring slot
        if (t + 1 < 9) {
            const uint4* wp = g_wf + (size_t)(t + 1) * 512;
            uint32_t dst = smb + OFF_WB + (uint32_t)((t + 1) & 1) * 8192u;
#pragma unroll
            for (int i = tid; i < 512; i += 256)
                sts128(dst + (uint32_t)i * 16u, __ldg(wp + i));
        }

        const int kh = t / 3, kw = t % 3;
        // A base: staged row (wid + kh), col (xh*16 + lane&15 + kw)
        const uint32_t arow0 = (uint32_t)((wid + kh) * IW + kw) * 128u;
        const uint32_t wbuf = smb + OFF_WB + (uint32_t)(t & 1) * 8192u + bln;
#pragma unroll
        for (int c = 0; c < 4; c++) {
            // B fragments for ALL 64 co: 4 conflict-free lds.128
            const uint32_t cb = wbuf + (uint32_t)c * 2048u;
            uint4 B0 = lds128(cb);            // wn0 half0: g0,g1
            uint4 B1 = lds128(cb + 512u);     // wn0 half1: g2,g3
            uint4 B2 = lds128(cb + 1024u);    // wn1 half0: g4,g5
            uint4 B3 = lds128(cb + 1536u);    // wn1 half1: g6,g7
            const uint32_t kofs = (uint32_t)c * 32u + acol;
#pragma unroll
            for (int xh = 0; xh < 2; xh++) {
                uint32_t a0, a1, a2, a3;
                uint32_t off = arow0 + (alx + (uint32_t)(xh * 16)) * 128u + kofs;
                ldm_x4(a0, a1, a2, a3, smb + swz(off));
                mma16816(acc[xh][0], a0, a1, a2, a3, B0.x, B0.y);
                mma16816(acc[xh][1], a0, a1, a2, a3, B0.z, B0.w);
                mma16816(acc[xh][2], a0, a1, a2, a3, B1.x, B1.y);
                mma16816(acc[xh][3], a0, a1, a2, a3, B1.z, B1.w);
                mma16816(acc[xh][4], a0, a1, a2, a3, B2.x, B2.y);
                mma16816(acc[xh][5], a0, a1, a2, a3, B2.z, B2.w);
                mma16816(acc[xh][6], a0, a1, a2, a3, B3.x, B3.y);
                mma16816(acc[xh][7], a0, a1, a2, a3, B3.z, B3.w);
            }
        }
        __syncthreads();   // ring-slot rotation barrier
    }

    // ---- epilogue: bias + store ----
    const int r0 = lane >> 2, c0 = (lane & 3) * 2;
    float bl[8], bh[8];
#pragma unroll
    for (int g = 0; g < 8; g++) {
        int co = g * 8 + c0;
        bl[g] = __ldg(bias + co);
        bh[g] = __ldg(bias + co + 1);
    }
    const int y = y0 + wid;
#pragma unroll
    for (int xh = 0; xh < 2; xh++) {
        int xb = x0 + xh * 16;
#pragma unroll
        for (int g = 0; g < 8; g++) {
            int co = g * 8 + c0;
            float* o0 = out + (((size_t)n * CH + co)     * HH + y) * WW + xb;
            float* o1 = out + (((size_t)n * CH + co + 1) * HH + y) * WW + xb;
            o0[r0]     = acc[xh][g][0] + bl[g];
            o1[r0]     = acc[xh][g][1] + bh[g];
            o0[r0 + 8] = acc[xh][g][2] + bl[g];
            o1[r0 + 8] = acc[xh][g][3] + bh[g];
        }
    }
}

extern "C" void kernel_launch(void* const* d_in, const int* in_sizes, int n_in,
                              void* d_out, int out_size) {
    const float* x    = (const float*)d_in[0];   // [32,64,224,224]
    const float* w    = (const float*)d_in[1];   // [64,64,3,3]
    const float* bias = (const float*)d_in[2];   // [64]
    float* out = (float*)d_out;

    prep_wfrag<<<(9 * 4 * 2 * 2 * 32 + 255) / 256, 256>>>(w);

    cudaFuncSetAttribute(bconv_mma, cudaFuncAttributeMaxDynamicSharedMemorySize, SMEM_DYN);
    dim3 grid(WW / TPX, HH / TRY, 32);   // (7, 28, 32) = 6272 CTAs
    bconv_mma<<<grid, 256, SMEM_DYN>>>(x, bias, out);
}

// round 14
// speedup vs baseline: 1.4671x; 1.4671x over previous
#include <cuda_runtime.h>
#include <cuda_fp16.h>
#include <stdint.h>

#define CH 64
#define HH 224
#define WW 224
#define HW (HH*WW)

#define TPX 32          // output tile width
#define TRY 8           // output tile rows
#define IW  34          // staged input width  (x0-1 .. x0+32)
#define IR  10          // staged input rows   (y0-1 .. y0+8)

#define P_BYTES (IR*IW*128)                 // 43520: fp16 plane [(r,q)][ci 0..63]
#define OFF_WB  ((uint32_t)P_BYTES)         // weight kw-slice ring: 2 x 24576 B
#define WSLICE  24576u
#define SMEM_DYN (P_BYTES + 2*WSLICE)       // 92672 B -> 2 CTAs/SM

// B fragments in mma.m16n8k16.f16 fragment order, kw-major slices:
// [kw][kh][c][wn][half][lane]; half0 = {g0,g1}, half1 = {g2,g3} (g rel. to wn*32)
// lane holds {B[k][n], B[k+1][n]}, n = wn*32+g*8+lane/4, k = 16c+(lane%4)*2+r2*8
__device__ uint4 g_wf[3 * 3 * 4 * 2 * 2 * 32];   // 73728 B (L2-resident)

__global__ void prep_wfrag(const float* __restrict__ w) {
    int idx = blockIdx.x * blockDim.x + threadIdx.x;
    if (idx >= 3 * 3 * 4 * 2 * 2 * 32) return;
    int lane = idx & 31;
    int half = (idx >> 5) & 1;
    int wn   = (idx >> 6) & 1;
    int c    = (idx >> 7) & 3;
    int kh   = (idx >> 9) % 3;
    int kw   = idx / (3 * 512);
    int tap  = kh * 3 + kw;
    uint32_t r[4];
#pragma unroll
    for (int j = 0; j < 4; j++) {
        int g  = half * 2 + (j >> 1);
        int r2 = j & 1;
        int n  = wn * 32 + g * 8 + (lane >> 2);
        int k  = c * 16 + (lane & 3) * 2 + r2 * 8;
        float v0 = w[(n * 64 + k)     * 9 + tap];
        float v1 = w[(n * 64 + k + 1) * 9 + tap];
        float s0 = (v0 > 0.f) ? 1.f : ((v0 < 0.f) ? -1.f : 0.f);
        float s1 = (v1 > 0.f) ? 1.f : ((v1 < 0.f) ? -1.f : 0.f);
        __half h0 = __float2half(s0), h1 = __float2half(s1);
        r[j] = (uint32_t)__half_as_ushort(h0) | ((uint32_t)__half_as_ushort(h1) << 16);
    }
    g_wf[idx] = make_uint4(r[0], r[1], r[2], r[3]);
}

__device__ __forceinline__ uint32_t smem_u32(const void* p) {
    uint32_t a;
    asm("{ .reg .u64 t; cvta.to.shared.u64 t, %1; cvt.u32.u64 %0, t; }" : "=r"(a) : "l"(p));
    return a;
}
__device__ __forceinline__ uint32_t swz(uint32_t off) {   // SW128-atom XOR swizzle
    return off ^ ((off >> 3) & 0x70);
}
__device__ __forceinline__ void sts32(uint32_t a, uint32_t v) {
    asm volatile("st.shared.b32 [%0], %1;" :: "r"(a), "r"(v));
}
__device__ __forceinline__ void cpasync16(uint32_t dst, const void* src) {
    asm volatile("cp.async.cg.shared.global [%0], [%1], 16;" :: "r"(dst), "l"(src));
}
__device__ __forceinline__ void cpasync_commit() {
    asm volatile("cp.async.commit_group;");
}
__device__ __forceinline__ void cpasync_wait0() {
    asm volatile("cp.async.wait_group 0;");
}
__device__ __forceinline__ uint4 lds128(uint32_t a) {
    uint4 v;
    asm volatile("ld.shared.v4.b32 {%0,%1,%2,%3}, [%4];"
                 : "=r"(v.x), "=r"(v.y), "=r"(v.z), "=r"(v.w) : "r"(a));
    return v;
}
__device__ __forceinline__ void ldm_x4(uint32_t& r0, uint32_t& r1, uint32_t& r2, uint32_t& r3,
                                       uint32_t addr) {
    asm volatile("ldmatrix.sync.aligned.m8n8.x4.shared.b16 {%0,%1,%2,%3}, [%4];"
                 : "=r"(r0), "=r"(r1), "=r"(r2), "=r"(r3) : "r"(addr));
}
__device__ __forceinline__ void mma16816(float* d, const uint32_t* a, uint32_t b0, uint32_t b1) {
    asm volatile("mma.sync.aligned.m16n8k16.row.col.f32.f16.f16.f32 "
                 "{%0,%1,%2,%3},{%4,%5,%6,%7},{%8,%9},{%0,%1,%2,%3};"
                 : "+f"(d[0]), "+f"(d[1]), "+f"(d[2]), "+f"(d[3])
                 : "r"(a[0]), "r"(a[1]), "r"(a[2]), "r"(a[3]), "r"(b0), "r"(b1));
}

__global__ void __launch_bounds__(256, 2)
bconv_mma(const float* __restrict__ x, const float* __restrict__ bias,
          float* __restrict__ out)
{
    extern __shared__ char smraw[];
    const uint32_t smb = smem_u32(smraw);
    const int tid = threadIdx.x, lane = tid & 31, wid = tid >> 5;
    const int n = blockIdx.z, x0 = blockIdx.x * TPX, y0 = blockIdx.y * TRY;

    // ---- prime weight kw-slice 0 -> buf 0 via cp.async (1536 x 16B) ----
#pragma unroll
    for (int i = tid; i < 1536; i += 256)
        cpasync16(smb + OFF_WB + (uint32_t)i * 16u, g_wf + i);
    cpasync_commit();

    // ---- stage fp16 input plane: (10 rows x 34 px) x 32 ci-pairs ----
    const float* xn = x + (size_t)n * CH * HW;
    for (int idx = tid; idx < IR * IW * 32; idx += 256) {
        int q  = idx % IW;
        int rc = idx / IW;
        int r  = rc % IR;
        int cp = rc / IR;                 // ci pair 0..31
        int gx = x0 - 1 + q, ry = y0 - 1 + r;
        float v0 = 0.f, v1 = 0.f;
        if (gx >= 0 && gx < WW && ry >= 0 && ry < HH) {
            const float* p = xn + (size_t)(cp * 2) * HW + (size_t)ry * WW + gx;
            v0 = __ldg(p);
            v1 = __ldg(p + HW);
        }
        __half h0 = __float2half(v0), h1 = __float2half(v1);
        uint32_t hp = (uint32_t)__half_as_ushort(h0) | ((uint32_t)__half_as_ushort(h1) << 16);
        sts32(smb + swz((uint32_t)(r * IW + q) * 128u + (uint32_t)cp * 4u), hp);
    }
    cpasync_wait0();
    __syncthreads();

    // ---- warp tiling: 4(M) x 2(N); warp tile M64 x N32 ----
    const int wn = wid & 1;          // co half
    const int wm = wid >> 1;         // pixel quarter: output rows {2wm, 2wm+1}

    const uint32_t acol = ((uint32_t)lane >> 4) * 16u;    // k-halves for A
    const uint32_t alx  = (uint32_t)(lane & 15);
    const uint32_t bln  = (uint32_t)wn * 1024u + (uint32_t)lane * 16u;

    float acc[4][4][4];               // [f=dy*2+xh][g][reg]
#pragma unroll
    for (int f = 0; f < 4; f++)
#pragma unroll
        for (int g = 0; g < 4; g++)
#pragma unroll
            for (int r = 0; r < 4; r++) acc[f][g][r] = 0.f;

#pragma unroll
    for (int kw = 0; kw < 3; kw++) {
        // prefetch next kw slice into the other ring buffer
        if (kw + 1 < 3) {
            const uint4* wp = g_wf + (size_t)(kw + 1) * 1536;
            uint32_t dst = smb + OFF_WB + (uint32_t)((kw + 1) & 1) * WSLICE;
#pragma unroll
            for (int i = tid; i < 1536; i += 256)
                cpasync16(dst + (uint32_t)i * 16u, wp + i);
            cpasync_commit();
        }

        const uint32_t wbuf = smb + OFF_WB + (uint32_t)(kw & 1) * WSLICE + bln;
#pragma unroll
        for (int c = 0; c < 4; c++) {
            // hoisted A: 8 fragments covering input rows 2wm..2wm+3, both xh chunks
            uint32_t A[4][2][4];
#pragma unroll
            for (int rr = 0; rr < 4; rr++)
#pragma unroll
                for (int xh = 0; xh < 2; xh++) {
                    uint32_t off = (uint32_t)((2 * wm + rr) * IW + kw) * 128u
                                 + (alx + (uint32_t)(xh * 16)) * 128u
                                 + (uint32_t)c * 32u + acol;
                    ldm_x4(A[rr][xh][0], A[rr][xh][1], A[rr][xh][2], A[rr][xh][3],
                           smb + swz(off));
                }
#pragma unroll
            for (int kh = 0; kh < 3; kh++) {
                const uint32_t cb = wbuf + (uint32_t)kh * 8192u + (uint32_t)c * 2048u;
                uint4 B0 = lds128(cb);           // half0: g0,g1
                uint4 B1 = lds128(cb + 512u);    // half1: g2,g3
#pragma unroll
                for (int dy = 0; dy < 2; dy++) {
                    const int rr = kh + dy;
#pragma unroll
                    for (int xh = 0; xh < 2; xh++) {
                        const int f = dy * 2 + xh;
                        mma16816(acc[f][0], A[rr][xh], B0.x, B0.y);
                        mma16816(acc[f][1], A[rr][xh], B0.z, B0.w);
                        mma16816(acc[f][2], A[rr][xh], B1.x, B1.y);
                        mma16816(acc[f][3], A[rr][xh], B1.z, B1.w);
                    }
                }
            }
        }
        cpasync_wait0();
        __syncthreads();   // ring rotation: next slice visible, old slice free
    }

    // ---- epilogue: bias + store ----
    const int r0 = lane >> 2, c0 = (lane & 3) * 2;
    float bl[4], bh[4];
#pragma unroll
    for (int g = 0; g < 4; g++) {
        int co = wn * 32 + g * 8 + c0;
        bl[g] = __ldg(bias + co);
        bh[g] = __ldg(bias + co + 1);
    }
#pragma unroll
    for (int f = 0; f < 4; f++) {
        int y  = y0 + 2 * wm + (f >> 1);
        int xb = x0 + (f & 1) * 16;
#pragma unroll
        for (int g = 0; g < 4; g++) {
            int co = wn * 32 + g * 8 + c0;
            float* o0 = out + (((size_t)n * CH + co)     * HH + y) * WW + xb;
            float* o1 = out + (((size_t)n * CH + co + 1) * HH + y) * WW + xb;
            o0[r0]     = acc[f][g][0] + bl[g];
            o1[r0]     = acc[f][g][1] + bh[g];
            o0[r0 + 8] = acc[f][g][2] + bl[g];
            o1[r0 + 8] = acc[f][g][3] + bh[g];
        }
    }
}

extern "C" void kernel_launch(void* const* d_in, const int* in_sizes, int n_in,
                              void* d_out, int out_size) {
    const float* x    = (const float*)d_in[0];   // [32,64,224,224]
    const float* w    = (const float*)d_in[1];   // [64,64,3,3]
    const float* bias = (const float*)d_in[2];   // [64]
    float* out = (float*)d_out;

    prep_wfrag<<<(3 * 3 * 4 * 2 * 2 * 32 + 255) / 256, 256>>>(w);

    cudaFuncSetAttribute(bconv_mma, cudaFuncAttributeMaxDynamicSharedMemorySize, SMEM_DYN);
    dim3 grid(WW / TPX, HH / TRY, 32);   // (7, 28, 32) = 6272 CTAs
    bconv_mma<<<grid, 256, SMEM_DYN>>>(x, bias, out);
}